// round 15
// baseline (speedup 1.0000x reference)
#include <cuda_runtime.h>
#include <cuda_fp16.h>
#include <cstdint>
#include <math.h>

#define M_TOTAL 16384
#define DT      1024
#define DL      768
#define LBL     4096
#define THRESH  0.4f

// ---------------- scratch (__device__ globals; no allocations allowed) ----------------
__device__ __half g_xh1[(size_t)M_TOTAL * DT];   // text split hi
__device__ __half g_xh2[(size_t)M_TOTAL * DT];   // text split lo
__device__ __half g_Wh1[(size_t)DL * DT];        // W split hi
__device__ __half g_Wh2[(size_t)DL * DT];        // W split lo
__device__ __half g_th1[(size_t)M_TOTAL * DL];   // t split hi
__device__ __half g_th2[(size_t)M_TOTAL * DL];   // t split lo
__device__ __half g_lbh1[(size_t)LBL * DL];      // labels split hi  [L][DL]
__device__ __half g_lbh2[(size_t)LBL * DL];      // labels split lo
__device__ __half g_wh[(size_t)M_TOTAL * LBL];   // softmax numerators fp16
__device__ __half g_lth[(size_t)DL * LBL];       // labels^T fp16 [DL][LBL]
__device__ float  g_part[(size_t)M_TOTAL * 64];  // per-row partial sums

// ---------------- PTX helpers ----------------
#define MMA16816(C, Ar, Br) \
    asm volatile("mma.sync.aligned.m16n8k16.row.col.f32.f16.f16.f32 " \
        "{%0,%1,%2,%3}, {%4,%5,%6,%7}, {%8,%9}, {%0,%1,%2,%3};" \
        : "+f"((C)[0]), "+f"((C)[1]), "+f"((C)[2]), "+f"((C)[3]) \
        : "r"((Ar)[0]), "r"((Ar)[1]), "r"((Ar)[2]), "r"((Ar)[3]), \
          "r"((Br)[0]), "r"((Br)[1]))

#define LDSM4(R0, R1, R2, R3, ADDR) \
    asm volatile("ldmatrix.sync.aligned.m8n8.x4.shared.b16 {%0,%1,%2,%3}, [%4];" \
        : "=r"(R0), "=r"(R1), "=r"(R2), "=r"(R3) : "r"(ADDR))

#define CPASYNC16(SMEM, GMEM) \
    asm volatile("cp.async.cg.shared.global [%0], [%1], 16;" \
        :: "r"(SMEM), "l"(GMEM))
#define CPCOMMIT() asm volatile("cp.async.commit_group;" ::: "memory")
#define CPWAIT(N)  asm volatile("cp.async.wait_group %0;" :: "n"(N) : "memory")

__device__ __forceinline__ uint32_t smem_u32(const void* p) {
    uint32_t a;
    asm("{ .reg .u64 t; cvta.to.shared.u64 t, %1; cvt.u32.u64 %0, t; }" : "=r"(a) : "l"(p));
    return a;
}

// ============ GEMM1: 128x128 CTA, 256 thr, 2-stage, 3 products (champion) ============
// t = text @ W^T + bias -> split-store (g_th1, g_th2).  KT=32.
__global__ __launch_bounds__(256, 2)
void gemm1_k(const __half* __restrict__ A1p, const __half* __restrict__ A2p,
             const __half* __restrict__ B1p, const __half* __restrict__ B2p,
             const float* __restrict__ bias)
{
    constexpr int KDIM = DT, NDIM = DL, KT = 32;
    constexpr int NCH    = KDIM / KT;
    constexpr int STRIDE = KT + 8;
    constexpr int TSIZE  = 128 * STRIDE;
    constexpr int NT     = 4;
    constexpr int CPT    = KT / 8;
    constexpr int PERTHR = (128 * CPT) / 256;

    extern __shared__ __align__(16) __half smh[];
    const uint32_t smb = smem_u32(smh);

    const int tid  = threadIdx.x;
    const int lane = tid & 31;
    const int wid  = tid >> 5;
    const int g    = lane >> 2;
    const int tig  = lane & 3;
    const int wm   = wid & 3;
    const int wn   = wid >> 2;
    const int mrow = wm * 32;
    const int ncol = wn * 64;
    const int mBase = blockIdx.y * 128;
    const int nBase = blockIdx.x * 128;

    const __half* Tg[4] = {
        A1p + (size_t)mBase * KDIM, A2p + (size_t)mBase * KDIM,
        B1p + (size_t)nBase * KDIM, B2p + (size_t)nBase * KDIM };

    const int a_off = (mrow + (lane & 7) + ((lane >> 3) & 1) * 8) * STRIDE + ((lane >> 4) & 1) * 8;
    const int b_off = (ncol + (lane & 7) + ((lane >> 4) & 1) * 8) * STRIDE + ((lane >> 3) & 1) * 8;

    float acc[2][8][4];
    #pragma unroll
    for (int mt = 0; mt < 2; mt++)
        #pragma unroll
        for (int nt = 0; nt < 8; nt++)
            #pragma unroll
            for (int e = 0; e < 4; e++) acc[mt][nt][e] = 0.f;

    auto ISSUE = [&](int kb, int buf) {
        #pragma unroll
        for (int tl = 0; tl < NT; tl++) {
            #pragma unroll
            for (int t = 0; t < PERTHR; t++) {
                const int idx = tid + t * 256;
                const int r = idx / CPT, c16 = idx % CPT;
                CPASYNC16(smb + ((buf * NT + tl) * TSIZE + r * STRIDE) * 2 + c16 * 16,
                          Tg[tl] + (size_t)r * KDIM + kb * KT + c16 * 8);
            }
        }
        CPCOMMIT();
    };

    ISSUE(0, 0);

    for (int kb = 0; kb < NCH; kb++) {
        const int buf = kb & 1;
        const bool more = (kb + 1) < NCH;
        if (more) { ISSUE(kb + 1, buf ^ 1); CPWAIT(1); }
        else      { CPWAIT(0); }
        __syncthreads();

        const uint32_t tA1 = smb + ((buf * NT + 0) * TSIZE) * 2;
        const uint32_t tA2 = smb + ((buf * NT + 1) * TSIZE) * 2;
        const uint32_t tB1 = smb + ((buf * NT + 2) * TSIZE) * 2;
        const uint32_t tB2 = smb + ((buf * NT + 3) * TSIZE) * 2;

        #pragma unroll
        for (int ks = 0; ks < KT; ks += 16) {
            uint32_t Af1[2][4], Af2[2][4], Bf[4][4];

            #pragma unroll
            for (int mt = 0; mt < 2; mt++)
                LDSM4(Af1[mt][0], Af1[mt][1], Af1[mt][2], Af1[mt][3],
                      tA1 + (a_off + mt * 16 * STRIDE + ks) * 2);
            #pragma unroll
            for (int mt = 0; mt < 2; mt++)
                LDSM4(Af2[mt][0], Af2[mt][1], Af2[mt][2], Af2[mt][3],
                      tA2 + (a_off + mt * 16 * STRIDE + ks) * 2);
            #pragma unroll
            for (int p = 0; p < 4; p++)
                LDSM4(Bf[p][0], Bf[p][1], Bf[p][2], Bf[p][3],
                      tB1 + (b_off + p * 16 * STRIDE + ks) * 2);

            #pragma unroll
            for (int p = 0; p < 4; p++)
                #pragma unroll
                for (int mt = 0; mt < 2; mt++) {
                    MMA16816(acc[mt][p * 2 + 0], Af1[mt], &Bf[p][0]);
                    MMA16816(acc[mt][p * 2 + 1], Af1[mt], &Bf[p][2]);
                }
            #pragma unroll
            for (int p = 0; p < 4; p++)
                #pragma unroll
                for (int mt = 0; mt < 2; mt++) {
                    MMA16816(acc[mt][p * 2 + 0], Af2[mt], &Bf[p][0]);
                    MMA16816(acc[mt][p * 2 + 1], Af2[mt], &Bf[p][2]);
                }
            #pragma unroll
            for (int p = 0; p < 4; p++)
                LDSM4(Bf[p][0], Bf[p][1], Bf[p][2], Bf[p][3],
                      tB2 + (b_off + p * 16 * STRIDE + ks) * 2);
            #pragma unroll
            for (int p = 0; p < 4; p++)
                #pragma unroll
                for (int mt = 0; mt < 2; mt++) {
                    MMA16816(acc[mt][p * 2 + 0], Af1[mt], &Bf[p][0]);
                    MMA16816(acc[mt][p * 2 + 1], Af1[mt], &Bf[p][2]);
                }
        }
        __syncthreads();
    }

    #pragma unroll
    for (int mt = 0; mt < 2; mt++) {
        #pragma unroll
        for (int nt = 0; nt < 8; nt++) {
            const int r0 = mBase + mrow + mt * 16 + g;
            const int r1 = r0 + 8;
            const int c  = nBase + ncol + nt * 8 + tig * 2;
            float v0 = acc[mt][nt][0] + bias[c];
            float v1 = acc[mt][nt][1] + bias[c + 1];
            float v2 = acc[mt][nt][2] + bias[c];
            float v3 = acc[mt][nt][3] + bias[c + 1];
            __half2 h0 = __floats2half2_rn(v0, v1);
            __half2 h1 = __floats2half2_rn(v2, v3);
            float2 f0 = __half22float2(h0), f1 = __half22float2(h1);
            __half2 l0 = __floats2half2_rn(v0 - f0.x, v1 - f0.y);
            __half2 l1 = __floats2half2_rn(v2 - f1.x, v3 - f1.y);
            *(__half2*)(g_th1 + (size_t)r0 * NDIM + c) = h0;
            *(__half2*)(g_th1 + (size_t)r1 * NDIM + c) = h1;
            *(__half2*)(g_th2 + (size_t)r0 * NDIM + c) = l0;
            *(__half2*)(g_th2 + (size_t)r1 * NDIM + c) = l1;
        }
    }
}

// ============ GEMM2 wide: 128x256 CTA, 512 thr, KT=64, 2-stage, 3 products ============
__global__ __launch_bounds__(512, 1)
void gemm2_wide(const __half* __restrict__ A1p, const __half* __restrict__ A2p,
                const __half* __restrict__ B1p, const __half* __restrict__ B2p)
{
    constexpr int KDIM = DL, NDIM = LBL, KT = 64;
    constexpr int NCH    = KDIM / KT;          // 12
    constexpr int STRIDE = KT + 8;             // 72
    constexpr int ASZ    = 128 * STRIDE;
    constexpr int BSZ    = 256 * STRIDE;
    constexpr int STG    = 2 * ASZ + 2 * BSZ;

    extern __shared__ __align__(16) __half smh[];
    const uint32_t smb = smem_u32(smh);

    const int tid  = threadIdx.x;
    const int wid  = tid >> 5;
    const int lane = tid & 31;
    const int g    = lane >> 2;
    const int tig  = lane & 3;
    const int wm   = wid & 3;
    const int wn   = wid >> 2;
    const int mrow = wm * 32;
    const int ncol = wn * 64;
    const int mBase = blockIdx.y * 128;
    const int nBase = blockIdx.x * 256;

    const __half* Ag1 = A1p + (size_t)mBase * KDIM;
    const __half* Ag2 = A2p + (size_t)mBase * KDIM;
    const __half* Bg1 = B1p + (size_t)nBase * KDIM;
    const __half* Bg2 = B2p + (size_t)nBase * KDIM;

    const int a_off = (mrow + (lane & 7) + ((lane >> 3) & 1) * 8) * STRIDE + ((lane >> 4) & 1) * 8;
    const int b_off = (ncol + (lane & 7) + ((lane >> 4) & 1) * 8) * STRIDE + ((lane >> 3) & 1) * 8;

    float acc[2][8][4];
    #pragma unroll
    for (int mt = 0; mt < 2; mt++)
        #pragma unroll
        for (int nt = 0; nt < 8; nt++)
            #pragma unroll
            for (int e = 0; e < 4; e++) acc[mt][nt][e] = 0.f;

    auto ISSUE = [&](int kb, int buf) {
        const uint32_t sbase = smb + (uint32_t)buf * STG * 2;
        #pragma unroll
        for (int t = 0; t < 2; t++) {
            const int idx = tid + t * 512;
            const int r = idx >> 3, c16 = idx & 7;
            CPASYNC16(sbase + (0 * ASZ + r * STRIDE) * 2 + c16 * 16,
                      Ag1 + (size_t)r * KDIM + kb * KT + c16 * 8);
        }
        #pragma unroll
        for (int t = 0; t < 2; t++) {
            const int idx = tid + t * 512;
            const int r = idx >> 3, c16 = idx & 7;
            CPASYNC16(sbase + (1 * ASZ + r * STRIDE) * 2 + c16 * 16,
                      Ag2 + (size_t)r * KDIM + kb * KT + c16 * 8);
        }
        #pragma unroll
        for (int t = 0; t < 4; t++) {
            const int idx = tid + t * 512;
            const int r = idx >> 3, c16 = idx & 7;
            CPASYNC16(sbase + (2 * ASZ + r * STRIDE) * 2 + c16 * 16,
                      Bg1 + (size_t)r * KDIM + kb * KT + c16 * 8);
        }
        #pragma unroll
        for (int t = 0; t < 4; t++) {
            const int idx = tid + t * 512;
            const int r = idx >> 3, c16 = idx & 7;
            CPASYNC16(sbase + (2 * ASZ + BSZ + r * STRIDE) * 2 + c16 * 16,
                      Bg2 + (size_t)r * KDIM + kb * KT + c16 * 8);
        }
        CPCOMMIT();
    };

    ISSUE(0, 0);

    for (int kb = 0; kb < NCH; kb++) {
        const int buf = kb & 1;
        const bool more = (kb + 1) < NCH;
        if (more) { ISSUE(kb + 1, buf ^ 1); CPWAIT(1); }
        else      { CPWAIT(0); }
        __syncthreads();

        const uint32_t tA1 = smb + ((uint32_t)buf * STG + 0 * ASZ) * 2;
        const uint32_t tA2 = smb + ((uint32_t)buf * STG + 1 * ASZ) * 2;
        const uint32_t tB1 = smb + ((uint32_t)buf * STG + 2 * ASZ) * 2;
        const uint32_t tB2 = smb + ((uint32_t)buf * STG + 2 * ASZ + BSZ) * 2;

        #pragma unroll
        for (int ks = 0; ks < KT; ks += 16) {
            uint32_t Af1[2][4], Af2[2][4], Bf[4][4];

            #pragma unroll
            for (int mt = 0; mt < 2; mt++)
                LDSM4(Af1[mt][0], Af1[mt][1], Af1[mt][2], Af1[mt][3],
                      tA1 + (a_off + mt * 16 * STRIDE + ks) * 2);
            #pragma unroll
            for (int mt = 0; mt < 2; mt++)
                LDSM4(Af2[mt][0], Af2[mt][1], Af2[mt][2], Af2[mt][3],
                      tA2 + (a_off + mt * 16 * STRIDE + ks) * 2);
            #pragma unroll
            for (int p = 0; p < 4; p++)
                LDSM4(Bf[p][0], Bf[p][1], Bf[p][2], Bf[p][3],
                      tB1 + (b_off + p * 16 * STRIDE + ks) * 2);

            #pragma unroll
            for (int p = 0; p < 4; p++)
                #pragma unroll
                for (int mt = 0; mt < 2; mt++) {
                    MMA16816(acc[mt][p * 2 + 0], Af1[mt], &Bf[p][0]);
                    MMA16816(acc[mt][p * 2 + 1], Af1[mt], &Bf[p][2]);
                }
            #pragma unroll
            for (int p = 0; p < 4; p++)
                #pragma unroll
                for (int mt = 0; mt < 2; mt++) {
                    MMA16816(acc[mt][p * 2 + 0], Af2[mt], &Bf[p][0]);
                    MMA16816(acc[mt][p * 2 + 1], Af2[mt], &Bf[p][2]);
                }
            #pragma unroll
            for (int p = 0; p < 4; p++)
                LDSM4(Bf[p][0], Bf[p][1], Bf[p][2], Bf[p][3],
                      tB2 + (b_off + p * 16 * STRIDE + ks) * 2);
            #pragma unroll
            for (int p = 0; p < 4; p++)
                #pragma unroll
                for (int mt = 0; mt < 2; mt++) {
                    MMA16816(acc[mt][p * 2 + 0], Af1[mt], &Bf[p][0]);
                    MMA16816(acc[mt][p * 2 + 1], Af1[mt], &Bf[p][2]);
                }
        }
        __syncthreads();
    }

    // ---- epilogue: sigmoid/threshold/exp + partial rowsums ----
    float rs[2][2] = {{0.f, 0.f}, {0.f, 0.f}};

    #pragma unroll
    for (int mt = 0; mt < 2; mt++) {
        #pragma unroll
        for (int nt = 0; nt < 8; nt++) {
            const int r0 = mBase + mrow + mt * 16 + g;
            const int r1 = r0 + 8;
            const int c  = nBase + ncol + nt * 8 + tig * 2;
            float v0 = acc[mt][nt][0], v1 = acc[mt][nt][1];
            float v2 = acc[mt][nt][2], v3 = acc[mt][nt][3];

            float a0 = __fdividef(1.f, 1.f + __expf(-v0)); if (a0 < THRESH) a0 = 0.f;
            float a1 = __fdividef(1.f, 1.f + __expf(-v1)); if (a1 < THRESH) a1 = 0.f;
            float a2 = __fdividef(1.f, 1.f + __expf(-v2)); if (a2 < THRESH) a2 = 0.f;
            float a3 = __fdividef(1.f, 1.f + __expf(-v3)); if (a3 < THRESH) a3 = 0.f;
            v0 = __expf(a0); v1 = __expf(a1); v2 = __expf(a2); v3 = __expf(a3);
            rs[mt][0] += v0 + v1;
            rs[mt][1] += v2 + v3;
            *(__half2*)(g_wh + (size_t)r0 * NDIM + c) = __floats2half2_rn(v0, v1);
            *(__half2*)(g_wh + (size_t)r1 * NDIM + c) = __floats2half2_rn(v2, v3);
        }
    }

    #pragma unroll
    for (int mt = 0; mt < 2; mt++)
        #pragma unroll
        for (int h = 0; h < 2; h++) {
            rs[mt][h] += __shfl_xor_sync(0xffffffffu, rs[mt][h], 1);
            rs[mt][h] += __shfl_xor_sync(0xffffffffu, rs[mt][h], 2);
        }
    __syncthreads();
    float* red = (float*)smh;                  // [128 rows][4 n-warps]
    if (tig == 0) {
        red[(mrow + g)      * 4 + wn] = rs[0][0];
        red[(mrow + g + 8)  * 4 + wn] = rs[0][1];
        red[(mrow + g + 16) * 4 + wn] = rs[1][0];
        red[(mrow + g + 24) * 4 + wn] = rs[1][1];
    }
    __syncthreads();
    if (tid < 128)
        g_part[(size_t)(mBase + tid) * 64 + blockIdx.x] =
            (red[tid * 4 + 0] + red[tid * 4 + 1]) + (red[tid * 4 + 2] + red[tid * 4 + 3]);
}

// ============ GEMM3 wide: 128x256 CTA, 512 thr, KT=64, 2-stage, 1 product ============
// out = (w @ labels) * inv ; inv computed in-prologue from g_part (replaces rowinv_k)
__global__ __launch_bounds__(512, 1)
void gemm3_wide(const __half* __restrict__ A1p, const __half* __restrict__ B1p,
                float* __restrict__ outp)
{
    constexpr int KDIM = LBL, NDIM = DL, KT = 64;
    constexpr int NCH    = KDIM / KT;          // 64
    constexpr int STRIDE = KT + 8;             // 72
    constexpr int ASZ    = 128 * STRIDE;
    constexpr int BSZ    = 256 * STRIDE;
    constexpr int STG    = ASZ + BSZ;          // 27648 halves

    extern __shared__ __align__(16) __half smh[];
    __shared__ float s_inv[128];
    const uint32_t smb = smem_u32(smh);

    const int tid  = threadIdx.x;
    const int wid  = tid >> 5;
    const int lane = tid & 31;
    const int g    = lane >> 2;
    const int tig  = lane & 3;
    const int wm   = wid & 3;
    const int wn   = wid >> 2;
    const int mrow = wm * 32;
    const int ncol = wn * 64;
    const int mBase = blockIdx.y * 128;
    const int nBase = blockIdx.x * 256;

    // fold rowinv: same summation order as the old rowinv_k -> bit-identical
    if (tid < 128) {
        float s = 0.f;
        #pragma unroll
        for (int p = 0; p < 16; p++) s += g_part[(size_t)(mBase + tid) * 64 + p];
        s_inv[tid] = 1.f / s;
    }

    const __half* Ag = A1p + (size_t)mBase * KDIM;
    const __half* Bg = B1p + (size_t)nBase * KDIM;

    const int a_off = (mrow + (lane & 7) + ((lane >> 3) & 1) * 8) * STRIDE + ((lane >> 4) & 1) * 8;
    const int b_off = (ncol + (lane & 7) + ((lane >> 4) & 1) * 8) * STRIDE + ((lane >> 3) & 1) * 8;

    float acc[2][8][4];
    #pragma unroll
    for (int mt = 0; mt < 2; mt++)
        #pragma unroll
        for (int nt = 0; nt < 8; nt++)
            #pragma unroll
            for (int e = 0; e < 4; e++) acc[mt][nt][e] = 0.f;

    auto ISSUE = [&](int kb, int buf) {
        const uint32_t sbase = smb + (uint32_t)buf * STG * 2;
        #pragma unroll
        for (int t = 0; t < 2; t++) {
            const int idx = tid + t * 512;
            const int r = idx >> 3, c16 = idx & 7;
            CPASYNC16(sbase + (r * STRIDE) * 2 + c16 * 16,
                      Ag + (size_t)r * KDIM + kb * KT + c16 * 8);
        }
        #pragma unroll
        for (int t = 0; t < 4; t++) {
            const int idx = tid + t * 512;
            const int r = idx >> 3, c16 = idx & 7;
            CPASYNC16(sbase + (ASZ + r * STRIDE) * 2 + c16 * 16,
                      Bg + (size_t)r * KDIM + kb * KT + c16 * 8);
        }
        CPCOMMIT();
    };

    ISSUE(0, 0);

    for (int kb = 0; kb < NCH; kb++) {
        const int buf = kb & 1;
        const bool more = (kb + 1) < NCH;
        if (more) { ISSUE(kb + 1, buf ^ 1); CPWAIT(1); }
        else      { CPWAIT(0); }
        __syncthreads();

        const uint32_t tA = smb + ((uint32_t)buf * STG) * 2;
        const uint32_t tB = smb + ((uint32_t)buf * STG + ASZ) * 2;

        #pragma unroll
        for (int ks = 0; ks < KT; ks += 16) {
            uint32_t Af[2][4], Bf[4][4];
            #pragma unroll
            for (int mt = 0; mt < 2; mt++)
                LDSM4(Af[mt][0], Af[mt][1], Af[mt][2], Af[mt][3],
                      tA + (a_off + mt * 16 * STRIDE + ks) * 2);
            #pragma unroll
            for (int p = 0; p < 4; p++)
                LDSM4(Bf[p][0], Bf[p][1], Bf[p][2], Bf[p][3],
                      tB + (b_off + p * 16 * STRIDE + ks) * 2);
            #pragma unroll
            for (int p = 0; p < 4; p++)
                #pragma unroll
                for (int mt = 0; mt < 2; mt++) {
                    MMA16816(acc[mt][p * 2 + 0], Af[mt], &Bf[p][0]);
                    MMA16816(acc[mt][p * 2 + 1], Af[mt], &Bf[p][2]);
                }
        }
        __syncthreads();
    }

    #pragma unroll
    for (int mt = 0; mt < 2; mt++) {
        #pragma unroll
        for (int nt = 0; nt < 8; nt++) {
            const int lr0 = mrow + mt * 16 + g;
            const int lr1 = lr0 + 8;
            const int r0 = mBase + lr0, r1 = mBase + lr1;
            const int c  = nBase + ncol + nt * 8 + tig * 2;
            const float i0 = s_inv[lr0], i1 = s_inv[lr1];
            *(float2*)(outp + (size_t)r0 * NDIM + c) =
                make_float2(acc[mt][nt][0] * i0, acc[mt][nt][1] * i0);
            *(float2*)(outp + (size_t)r1 * NDIM + c) =
                make_float2(acc[mt][nt][2] * i1, acc[mt][nt][3] * i1);
        }
    }
}

// ---------------- elementwise fp32 -> (h1,h2) split ----------------
__global__ void split_k(const float* __restrict__ src,
                        __half* __restrict__ d1, __half* __restrict__ d2, int n4)
{
    const int i = blockIdx.x * 256 + threadIdx.x;
    if (i >= n4) return;
    float4 x = ((const float4*)src)[i];
    __half2 h0 = __floats2half2_rn(x.x, x.y);
    __half2 h1 = __floats2half2_rn(x.z, x.w);
    float2 f0 = __half22float2(h0), f1 = __half22float2(h1);
    __half2 l0 = __floats2half2_rn(x.x - f0.x, x.y - f0.y);
    __half2 l1 = __floats2half2_rn(x.z - f1.x, x.w - f1.y);
    ((uint2*)d1)[i] = make_uint2(*(uint32_t*)&h0, *(uint32_t*)&h1);
    ((uint2*)d2)[i] = make_uint2(*(uint32_t*)&l0, *(uint32_t*)&l1);
}

// ---------------- labels transpose: [LBL][DL] fp32 -> g_lth [DL][LBL] fp16 ----------------
__global__ void transp_k(const float* __restrict__ in)
{
    __shared__ float t[32][33];
    const int bx = blockIdx.x * 32;   // DL dim
    const int by = blockIdx.y * 32;   // LBL dim
    const int x = threadIdx.x, y = threadIdx.y;
    #pragma unroll
    for (int j = 0; j < 32; j += 8)
        t[y + j][x] = in[(size_t)(by + y + j) * DL + bx + x];
    __syncthreads();
    #pragma unroll
    for (int j = 0; j < 32; j += 8)
        g_lth[(size_t)(bx + y + j) * LBL + by + x] = __float2half_rn(t[x][y + j]);
}

// ============================ host launcher ============================
#define SMEM_P3  (2 * 4 * 128 * 40 * 2)     // 81920 B  (GEMM1)
#define SMEM_G2  (2 * 55296 * 2)            // 221184 B (GEMM2 wide)
#define SMEM_G3  (2 * 27648 * 2)            // 110592 B (GEMM3 wide)

extern "C" void kernel_launch(void* const* d_in, const int* in_sizes, int n_in,
                              void* d_out, int out_size)
{
    const float* text   = (const float*)d_in[0];  // [8,2048,1024]
    const float* labels = (const float*)d_in[1];  // [4096,768]
    const float* W      = (const float*)d_in[2];  // [768,1024]
    const float* b      = (const float*)d_in[3];  // [768]
    float* out = (float*)d_out;                   // [8,2048,768]

    __half *xh1, *xh2, *Wh1, *Wh2, *th1, *th2, *lbh1, *lbh2, *wh, *lth;
    cudaGetSymbolAddress((void**)&xh1,  g_xh1);
    cudaGetSymbolAddress((void**)&xh2,  g_xh2);
    cudaGetSymbolAddress((void**)&Wh1,  g_Wh1);
    cudaGetSymbolAddress((void**)&Wh2,  g_Wh2);
    cudaGetSymbolAddress((void**)&th1,  g_th1);
    cudaGetSymbolAddress((void**)&th2,  g_th2);
    cudaGetSymbolAddress((void**)&lbh1, g_lbh1);
    cudaGetSymbolAddress((void**)&lbh2, g_lbh2);
    cudaGetSymbolAddress((void**)&wh,   g_wh);
    cudaGetSymbolAddress((void**)&lth,  g_lth);

    cudaFuncSetAttribute(gemm1_k,
                         cudaFuncAttributeMaxDynamicSharedMemorySize, SMEM_P3);
    cudaFuncSetAttribute(gemm2_wide,
                         cudaFuncAttributeMaxDynamicSharedMemorySize, SMEM_G2);
    cudaFuncSetAttribute(gemm3_wide,
                         cudaFuncAttributeMaxDynamicSharedMemorySize, SMEM_G3);

    // pre-split inputs to fp16 term pairs
    split_k<<<(M_TOTAL * DT / 4 + 255) / 256, 256>>>(text, xh1, xh2, M_TOTAL * DT / 4);
    split_k<<<(DL * DT / 4 + 255) / 256, 256>>>(W, Wh1, Wh2, DL * DT / 4);
    split_k<<<(LBL * DL / 4 + 255) / 256, 256>>>(labels, lbh1, lbh2, LBL * DL / 4);
    transp_k<<<dim3(DL / 32, LBL / 32), dim3(32, 8)>>>(labels);

    // K1: t = text @ W^T + b  (3-product) -> split-stored t
    gemm1_k<<<dim3(DL / 128, M_TOTAL / 128), 256, SMEM_P3>>>(xh1, xh2, Wh1, Wh2, b);

    // K2: w = exp(threshold(sigmoid(t @ labels^T)))  (wide 128x256 tiles)
    gemm2_wide<<<dim3(LBL / 256, M_TOTAL / 128), 512, SMEM_G2>>>(th1, th2, lbh1, lbh2);

    // K3: out = (w @ labels) * inv  (wide 128x256 tiles; rowinv folded in)
    gemm3_wide<<<dim3(DL / 256, M_TOTAL / 128), 512, SMEM_G3>>>(wh, lth, out);
}

// round 16
// speedup vs baseline: 1.0200x; 1.0200x over previous
#include <cuda_runtime.h>
#include <cuda_fp16.h>
#include <cstdint>
#include <math.h>

#define M_TOTAL 16384
#define DT      1024
#define DL      768
#define LBL     4096
#define THRESH  0.4f

// ---------------- scratch (__device__ globals; no allocations allowed) ----------------
__device__ __half g_xh1[(size_t)M_TOTAL * DT];   // text split hi
__device__ __half g_xh2[(size_t)M_TOTAL * DT];   // text split lo
__device__ __half g_Wh1[(size_t)DL * DT];        // W split hi
__device__ __half g_Wh2[(size_t)DL * DT];        // W split lo
__device__ __half g_th1[(size_t)M_TOTAL * DL];   // t split hi
__device__ __half g_th2[(size_t)M_TOTAL * DL];   // t split lo
__device__ __half g_lbh1[(size_t)LBL * DL];      // labels split hi  [L][DL]
__device__ __half g_lbh2[(size_t)LBL * DL];      // labels split lo
__device__ __half g_wh[(size_t)M_TOTAL * LBL];   // softmax numerators fp16
__device__ __half g_lth[(size_t)DL * LBL];       // labels^T fp16 [DL][LBL]
__device__ float  g_part[(size_t)M_TOTAL * 64];  // per-row partial sums

// ---------------- PTX helpers ----------------
#define MMA16816(C, Ar, Br) \
    asm volatile("mma.sync.aligned.m16n8k16.row.col.f32.f16.f16.f32 " \
        "{%0,%1,%2,%3}, {%4,%5,%6,%7}, {%8,%9}, {%0,%1,%2,%3};" \
        : "+f"((C)[0]), "+f"((C)[1]), "+f"((C)[2]), "+f"((C)[3]) \
        : "r"((Ar)[0]), "r"((Ar)[1]), "r"((Ar)[2]), "r"((Ar)[3]), \
          "r"((Br)[0]), "r"((Br)[1]))

#define LDSM4(R0, R1, R2, R3, ADDR) \
    asm volatile("ldmatrix.sync.aligned.m8n8.x4.shared.b16 {%0,%1,%2,%3}, [%4];" \
        : "=r"(R0), "=r"(R1), "=r"(R2), "=r"(R3) : "r"(ADDR))

#define CPASYNC16(SMEM, GMEM) \
    asm volatile("cp.async.cg.shared.global [%0], [%1], 16;" \
        :: "r"(SMEM), "l"(GMEM))
#define CPCOMMIT() asm volatile("cp.async.commit_group;" ::: "memory")
#define CPWAIT(N)  asm volatile("cp.async.wait_group %0;" :: "n"(N) : "memory")

__device__ __forceinline__ uint32_t smem_u32(const void* p) {
    uint32_t a;
    asm("{ .reg .u64 t; cvta.to.shared.u64 t, %1; cvt.u32.u64 %0, t; }" : "=r"(a) : "l"(p));
    return a;
}

// ============ champion HMMA GEMM: 128x128 CTA, 256 thr, 2-stage ============
// NPROD=3: acc = A1*B1 + A2*B1 + A1*B2 (KT=32);  NPROD=1: acc = A1*B1 (KT=64).
// MODE 0: t = acc + bias -> split-store (g_th1,g_th2)            [GEMM1]
// MODE 2: out = acc * inv[m], inv from g_part in-prologue        [GEMM3]
template<int KDIM, int NDIM, int KT, int NPROD, int MODE>
__global__ __launch_bounds__(256, 2)
void gemm_async(const __half* __restrict__ A1p, const __half* __restrict__ A2p,
                const __half* __restrict__ B1p, const __half* __restrict__ B2p,
                const float* __restrict__ bias, float* __restrict__ outp)
{
    constexpr int NCH    = KDIM / KT;
    constexpr int STRIDE = KT + 8;            // halves per smem row (pad 16B)
    constexpr int TSIZE  = 128 * STRIDE;      // halves per tile
    constexpr int NT     = (NPROD == 3) ? 4 : 2;   // tiles: A1[,A2],B1[,B2]
    constexpr int TB1    = (NPROD == 3) ? 2 : 1;
    constexpr int CPT    = KT / 8;            // 16B segs per row
    constexpr int PERTHR = (128 * CPT) / 256; // cp.async per thread per tile

    extern __shared__ __align__(16) __half smh[];
    __shared__ float s_inv[128];
    const uint32_t smb = smem_u32(smh);

    const int tid  = threadIdx.x;
    const int wid  = tid >> 5;
    const int lane = tid & 31;
    const int g    = lane >> 2;
    const int tig  = lane & 3;
    const int wm   = wid & 3;
    const int wn   = wid >> 2;
    const int mrow = wm * 32;
    const int ncol = wn * 64;
    const int mBase = blockIdx.y * 128;
    const int nBase = blockIdx.x * 128;

    // MODE 2: fold old rowinv_k (same summation order -> bit-identical)
    if (MODE == 2 && tid < 128) {
        float s = 0.f;
        #pragma unroll
        for (int p = 0; p < 16; p++) s += g_part[(size_t)(mBase + tid) * 64 + p];
        s_inv[tid] = 1.f / s;
    }

    const __half* Tg[4];
    Tg[0] = A1p + (size_t)mBase * KDIM;
    if (NPROD == 3) {
        Tg[1] = A2p + (size_t)mBase * KDIM;
        Tg[2] = B1p + (size_t)nBase * KDIM;
        Tg[3] = B2p + (size_t)nBase * KDIM;
    } else {
        Tg[1] = B1p + (size_t)nBase * KDIM;
    }

    const int a_off = (mrow + (lane & 7) + ((lane >> 3) & 1) * 8) * STRIDE + ((lane >> 4) & 1) * 8;
    const int b_off = (ncol + (lane & 7) + ((lane >> 4) & 1) * 8) * STRIDE + ((lane >> 3) & 1) * 8;

    float acc[2][8][4];
    #pragma unroll
    for (int mt = 0; mt < 2; mt++)
        #pragma unroll
        for (int nt = 0; nt < 8; nt++)
            #pragma unroll
            for (int e = 0; e < 4; e++) acc[mt][nt][e] = 0.f;

    auto ISSUE = [&](int kb, int buf) {
        #pragma unroll
        for (int tl = 0; tl < NT; tl++) {
            #pragma unroll
            for (int t = 0; t < PERTHR; t++) {
                const int idx = tid + t * 256;
                const int r = idx / CPT, c16 = idx % CPT;
                const uint32_t sa = smb + ((buf * NT + tl) * TSIZE + r * STRIDE) * 2 + c16 * 16;
                const __half* ga = Tg[tl] + (size_t)r * KDIM + kb * KT + c16 * 8;
                CPASYNC16(sa, ga);
            }
        }
        CPCOMMIT();
    };

    ISSUE(0, 0);

    for (int kb = 0; kb < NCH; kb++) {
        const int buf = kb & 1;
        const bool more = (kb + 1) < NCH;
        if (more) { ISSUE(kb + 1, buf ^ 1); CPWAIT(1); }
        else      { CPWAIT(0); }
        __syncthreads();

        const uint32_t tA1 = smb + ((buf * NT + 0) * TSIZE) * 2;
        const uint32_t tA2 = smb + ((buf * NT + 1) * TSIZE) * 2;
        const uint32_t tB1 = smb + ((buf * NT + TB1) * TSIZE) * 2;
        const uint32_t tB2 = smb + ((buf * NT + 3) * TSIZE) * 2;

        #pragma unroll
        for (int ks = 0; ks < KT; ks += 16) {
            uint32_t Af1[2][4], Af2[2][4], Bf[4][4];

            #pragma unroll
            for (int mt = 0; mt < 2; mt++)
                LDSM4(Af1[mt][0], Af1[mt][1], Af1[mt][2], Af1[mt][3],
                      tA1 + (a_off + mt * 16 * STRIDE + ks) * 2);
            if (NPROD == 3) {
                #pragma unroll
                for (int mt = 0; mt < 2; mt++)
                    LDSM4(Af2[mt][0], Af2[mt][1], Af2[mt][2], Af2[mt][3],
                          tA2 + (a_off + mt * 16 * STRIDE + ks) * 2);
            }
            #pragma unroll
            for (int p = 0; p < 4; p++)
                LDSM4(Bf[p][0], Bf[p][1], Bf[p][2], Bf[p][3],
                      tB1 + (b_off + p * 16 * STRIDE + ks) * 2);

            #pragma unroll
            for (int p = 0; p < 4; p++)
                #pragma unroll
                for (int mt = 0; mt < 2; mt++) {
                    MMA16816(acc[mt][p * 2 + 0], Af1[mt], &Bf[p][0]);
                    MMA16816(acc[mt][p * 2 + 1], Af1[mt], &Bf[p][2]);
                }

            if (NPROD == 3) {
                #pragma unroll
                for (int p = 0; p < 4; p++)
                    #pragma unroll
                    for (int mt = 0; mt < 2; mt++) {
                        MMA16816(acc[mt][p * 2 + 0], Af2[mt], &Bf[p][0]);
                        MMA16816(acc[mt][p * 2 + 1], Af2[mt], &Bf[p][2]);
                    }
                #pragma unroll
                for (int p = 0; p < 4; p++)
                    LDSM4(Bf[p][0], Bf[p][1], Bf[p][2], Bf[p][3],
                          tB2 + (b_off + p * 16 * STRIDE + ks) * 2);
                #pragma unroll
                for (int p = 0; p < 4; p++)
                    #pragma unroll
                    for (int mt = 0; mt < 2; mt++) {
                        MMA16816(acc[mt][p * 2 + 0], Af1[mt], &Bf[p][0]);
                        MMA16816(acc[mt][p * 2 + 1], Af1[mt], &Bf[p][2]);
                    }
            }
        }
        __syncthreads();
    }

    // ---------------- epilogue ----------------
    #pragma unroll
    for (int mt = 0; mt < 2; mt++) {
        #pragma unroll
        for (int nt = 0; nt < 8; nt++) {
            const int lr0 = mrow + mt * 16 + g;
            const int lr1 = lr0 + 8;
            const int r0 = mBase + lr0, r1 = mBase + lr1;
            const int c  = nBase + ncol + nt * 8 + tig * 2;
            float v0 = acc[mt][nt][0], v1 = acc[mt][nt][1];
            float v2 = acc[mt][nt][2], v3 = acc[mt][nt][3];

            if (MODE == 0) {
                const float b0 = bias[c], b1 = bias[c + 1];
                v0 += b0; v1 += b1; v2 += b0; v3 += b1;
                __half2 h0 = __floats2half2_rn(v0, v1);
                __half2 h1 = __floats2half2_rn(v2, v3);
                float2 f0 = __half22float2(h0), f1 = __half22float2(h1);
                __half2 l0 = __floats2half2_rn(v0 - f0.x, v1 - f0.y);
                __half2 l1 = __floats2half2_rn(v2 - f1.x, v3 - f1.y);
                *(__half2*)(g_th1 + (size_t)r0 * NDIM + c) = h0;
                *(__half2*)(g_th1 + (size_t)r1 * NDIM + c) = h1;
                *(__half2*)(g_th2 + (size_t)r0 * NDIM + c) = l0;
                *(__half2*)(g_th2 + (size_t)r1 * NDIM + c) = l1;
            } else {
                const float i0 = s_inv[lr0], i1 = s_inv[lr1];
                *(float2*)(outp + (size_t)r0 * NDIM + c) = make_float2(v0 * i0, v1 * i0);
                *(float2*)(outp + (size_t)r1 * NDIM + c) = make_float2(v2 * i1, v3 * i1);
            }
        }
    }
}

// ============ GEMM2 wide: 128x256 CTA, 512 thr, KT=64, 2-stage, 3 products ============
__global__ __launch_bounds__(512, 1)
void gemm2_wide(const __half* __restrict__ A1p, const __half* __restrict__ A2p,
                const __half* __restrict__ B1p, const __half* __restrict__ B2p)
{
    constexpr int KDIM = DL, NDIM = LBL, KT = 64;
    constexpr int NCH    = KDIM / KT;          // 12
    constexpr int STRIDE = KT + 8;             // 72
    constexpr int ASZ    = 128 * STRIDE;
    constexpr int BSZ    = 256 * STRIDE;
    constexpr int STG    = 2 * ASZ + 2 * BSZ;

    extern __shared__ __align__(16) __half smh[];
    const uint32_t smb = smem_u32(smh);

    const int tid  = threadIdx.x;
    const int wid  = tid >> 5;
    const int lane = tid & 31;
    const int g    = lane >> 2;
    const int tig  = lane & 3;
    const int wm   = wid & 3;
    const int wn   = wid >> 2;
    const int mrow = wm * 32;
    const int ncol = wn * 64;
    const int mBase = blockIdx.y * 128;
    const int nBase = blockIdx.x * 256;

    const __half* Ag1 = A1p + (size_t)mBase * KDIM;
    const __half* Ag2 = A2p + (size_t)mBase * KDIM;
    const __half* Bg1 = B1p + (size_t)nBase * KDIM;
    const __half* Bg2 = B2p + (size_t)nBase * KDIM;

    const int a_off = (mrow + (lane & 7) + ((lane >> 3) & 1) * 8) * STRIDE + ((lane >> 4) & 1) * 8;
    const int b_off = (ncol + (lane & 7) + ((lane >> 4) & 1) * 8) * STRIDE + ((lane >> 3) & 1) * 8;

    float acc[2][8][4];
    #pragma unroll
    for (int mt = 0; mt < 2; mt++)
        #pragma unroll
        for (int nt = 0; nt < 8; nt++)
            #pragma unroll
            for (int e = 0; e < 4; e++) acc[mt][nt][e] = 0.f;

    auto ISSUE = [&](int kb, int buf) {
        const uint32_t sbase = smb + (uint32_t)buf * STG * 2;
        #pragma unroll
        for (int t = 0; t < 2; t++) {
            const int idx = tid + t * 512;
            const int r = idx >> 3, c16 = idx & 7;
            CPASYNC16(sbase + (0 * ASZ + r * STRIDE) * 2 + c16 * 16,
                      Ag1 + (size_t)r * KDIM + kb * KT + c16 * 8);
        }
        #pragma unroll
        for (int t = 0; t < 2; t++) {
            const int idx = tid + t * 512;
            const int r = idx >> 3, c16 = idx & 7;
            CPASYNC16(sbase + (1 * ASZ + r * STRIDE) * 2 + c16 * 16,
                      Ag2 + (size_t)r * KDIM + kb * KT + c16 * 8);
        }
        #pragma unroll
        for (int t = 0; t < 4; t++) {
            const int idx = tid + t * 512;
            const int r = idx >> 3, c16 = idx & 7;
            CPASYNC16(sbase + (2 * ASZ + r * STRIDE) * 2 + c16 * 16,
                      Bg1 + (size_t)r * KDIM + kb * KT + c16 * 8);
        }
        #pragma unroll
        for (int t = 0; t < 4; t++) {
            const int idx = tid + t * 512;
            const int r = idx >> 3, c16 = idx & 7;
            CPASYNC16(sbase + (2 * ASZ + BSZ + r * STRIDE) * 2 + c16 * 16,
                      Bg2 + (size_t)r * KDIM + kb * KT + c16 * 8);
        }
        CPCOMMIT();
    };

    ISSUE(0, 0);

    for (int kb = 0; kb < NCH; kb++) {
        const int buf = kb & 1;
        const bool more = (kb + 1) < NCH;
        if (more) { ISSUE(kb + 1, buf ^ 1); CPWAIT(1); }
        else      { CPWAIT(0); }
        __syncthreads();

        const uint32_t tA1 = smb + ((uint32_t)buf * STG + 0 * ASZ) * 2;
        const uint32_t tA2 = smb + ((uint32_t)buf * STG + 1 * ASZ) * 2;
        const uint32_t tB1 = smb + ((uint32_t)buf * STG + 2 * ASZ) * 2;
        const uint32_t tB2 = smb + ((uint32_t)buf * STG + 2 * ASZ + BSZ) * 2;

        #pragma unroll
        for (int ks = 0; ks < KT; ks += 16) {
            uint32_t Af1[2][4], Af2[2][4], Bf[4][4];

            #pragma unroll
            for (int mt = 0; mt < 2; mt++)
                LDSM4(Af1[mt][0], Af1[mt][1], Af1[mt][2], Af1[mt][3],
                      tA1 + (a_off + mt * 16 * STRIDE + ks) * 2);
            #pragma unroll
            for (int mt = 0; mt < 2; mt++)
                LDSM4(Af2[mt][0], Af2[mt][1], Af2[mt][2], Af2[mt][3],
                      tA2 + (a_off + mt * 16 * STRIDE + ks) * 2);
            #pragma unroll
            for (int p = 0; p < 4; p++)
                LDSM4(Bf[p][0], Bf[p][1], Bf[p][2], Bf[p][3],
                      tB1 + (b_off + p * 16 * STRIDE + ks) * 2);

            #pragma unroll
            for (int p = 0; p < 4; p++)
                #pragma unroll
                for (int mt = 0; mt < 2; mt++) {
                    MMA16816(acc[mt][p * 2 + 0], Af1[mt], &Bf[p][0]);
                    MMA16816(acc[mt][p * 2 + 1], Af1[mt], &Bf[p][2]);
                }
            #pragma unroll
            for (int p = 0; p < 4; p++)
                #pragma unroll
                for (int mt = 0; mt < 2; mt++) {
                    MMA16816(acc[mt][p * 2 + 0], Af2[mt], &Bf[p][0]);
                    MMA16816(acc[mt][p * 2 + 1], Af2[mt], &Bf[p][2]);
                }
            #pragma unroll
            for (int p = 0; p < 4; p++)
                LDSM4(Bf[p][0], Bf[p][1], Bf[p][2], Bf[p][3],
                      tB2 + (b_off + p * 16 * STRIDE + ks) * 2);
            #pragma unroll
            for (int p = 0; p < 4; p++)
                #pragma unroll
                for (int mt = 0; mt < 2; mt++) {
                    MMA16816(acc[mt][p * 2 + 0], Af1[mt], &Bf[p][0]);
                    MMA16816(acc[mt][p * 2 + 1], Af1[mt], &Bf[p][2]);
                }
        }
        __syncthreads();
    }

    // ---- epilogue: sigmoid/threshold/exp + partial rowsums ----
    float rs[2][2] = {{0.f, 0.f}, {0.f, 0.f}};

    #pragma unroll
    for (int mt = 0; mt < 2; mt++) {
        #pragma unroll
        for (int nt = 0; nt < 8; nt++) {
            const int r0 = mBase + mrow + mt * 16 + g;
            const int r1 = r0 + 8;
            const int c  = nBase + ncol + nt * 8 + tig * 2;
            float v0 = acc[mt][nt][0], v1 = acc[mt][nt][1];
            float v2 = acc[mt][nt][2], v3 = acc[mt][nt][3];

            float a0 = __fdividef(1.f, 1.f + __expf(-v0)); if (a0 < THRESH) a0 = 0.f;
            float a1 = __fdividef(1.f, 1.f + __expf(-v1)); if (a1 < THRESH) a1 = 0.f;
            float a2 = __fdividef(1.f, 1.f + __expf(-v2)); if (a2 < THRESH) a2 = 0.f;
            float a3 = __fdividef(1.f, 1.f + __expf(-v3)); if (a3 < THRESH) a3 = 0.f;
            v0 = __expf(a0); v1 = __expf(a1); v2 = __expf(a2); v3 = __expf(a3);
            rs[mt][0] += v0 + v1;
            rs[mt][1] += v2 + v3;
            *(__half2*)(g_wh + (size_t)r0 * NDIM + c) = __floats2half2_rn(v0, v1);
            *(__half2*)(g_wh + (size_t)r1 * NDIM + c) = __floats2half2_rn(v2, v3);
        }
    }

    #pragma unroll
    for (int mt = 0; mt < 2; mt++)
        #pragma unroll
        for (int h = 0; h < 2; h++) {
            rs[mt][h] += __shfl_xor_sync(0xffffffffu, rs[mt][h], 1);
            rs[mt][h] += __shfl_xor_sync(0xffffffffu, rs[mt][h], 2);
        }
    __syncthreads();
    float* red = (float*)smh;                  // [128 rows][4 n-warps]
    if (tig == 0) {
        red[(mrow + g)      * 4 + wn] = rs[0][0];
        red[(mrow + g + 8)  * 4 + wn] = rs[0][1];
        red[(mrow + g + 16) * 4 + wn] = rs[1][0];
        red[(mrow + g + 24) * 4 + wn] = rs[1][1];
    }
    __syncthreads();
    if (tid < 128)
        g_part[(size_t)(mBase + tid) * 64 + blockIdx.x] =
            (red[tid * 4 + 0] + red[tid * 4 + 1]) + (red[tid * 4 + 2] + red[tid * 4 + 3]);
}

// ---------------- elementwise fp32 -> (h1,h2) split ----------------
__global__ void split_k(const float* __restrict__ src,
                        __half* __restrict__ d1, __half* __restrict__ d2, int n4)
{
    const int i = blockIdx.x * 256 + threadIdx.x;
    if (i >= n4) return;
    float4 x = ((const float4*)src)[i];
    __half2 h0 = __floats2half2_rn(x.x, x.y);
    __half2 h1 = __floats2half2_rn(x.z, x.w);
    float2 f0 = __half22float2(h0), f1 = __half22float2(h1);
    __half2 l0 = __floats2half2_rn(x.x - f0.x, x.y - f0.y);
    __half2 l1 = __floats2half2_rn(x.z - f1.x, x.w - f1.y);
    ((uint2*)d1)[i] = make_uint2(*(uint32_t*)&h0, *(uint32_t*)&h1);
    ((uint2*)d2)[i] = make_uint2(*(uint32_t*)&l0, *(uint32_t*)&l1);
}

// ------- fused labels pass: split -> (g_lbh1, g_lbh2)  AND  transpose -> g_lth -------
__global__ void labels_prep_k(const float* __restrict__ in)
{
    __shared__ float t[32][33];
    const int bx = blockIdx.x * 32;   // DL dim
    const int by = blockIdx.y * 32;   // LBL dim
    const int x = threadIdx.x, y = threadIdx.y;

    #pragma unroll
    for (int j = 0; j < 32; j += 8) {
        const size_t idx = (size_t)(by + y + j) * DL + bx + x;
        const float v = in[idx];
        t[y + j][x] = v;
        // split store (same rounding as split_k -> identical values)
        const __half h1 = __float2half_rn(v);
        const __half h2 = __float2half_rn(v - __half2float(h1));
        g_lbh1[idx] = h1;
        g_lbh2[idx] = h2;
    }
    __syncthreads();
    #pragma unroll
    for (int j = 0; j < 32; j += 8)
        g_lth[(size_t)(bx + y + j) * LBL + by + x] = __float2half_rn(t[x][y + j]);
}

// ============================ host launcher ============================
#define SMEM_P3 (2 * 4 * 128 * 40 * 2)     // 81920 B  (GEMM1: NPROD=3, KT=32)
#define SMEM_P1 (2 * 2 * 128 * 72 * 2)     // 73728 B  (GEMM3: NPROD=1, KT=64)
#define SMEM_G2 (2 * 55296 * 2)            // 221184 B (GEMM2 wide)

extern "C" void kernel_launch(void* const* d_in, const int* in_sizes, int n_in,
                              void* d_out, int out_size)
{
    const float* text   = (const float*)d_in[0];  // [8,2048,1024]
    const float* labels = (const float*)d_in[1];  // [4096,768]
    const float* W      = (const float*)d_in[2];  // [768,1024]
    const float* b      = (const float*)d_in[3];  // [768]
    float* out = (float*)d_out;                   // [8,2048,768]

    __half *xh1, *xh2, *Wh1, *Wh2, *th1, *th2, *lbh1, *lbh2, *wh, *lth;
    cudaGetSymbolAddress((void**)&xh1,  g_xh1);
    cudaGetSymbolAddress((void**)&xh2,  g_xh2);
    cudaGetSymbolAddress((void**)&Wh1,  g_Wh1);
    cudaGetSymbolAddress((void**)&Wh2,  g_Wh2);
    cudaGetSymbolAddress((void**)&th1,  g_th1);
    cudaGetSymbolAddress((void**)&th2,  g_th2);
    cudaGetSymbolAddress((void**)&lbh1, g_lbh1);
    cudaGetSymbolAddress((void**)&lbh2, g_lbh2);
    cudaGetSymbolAddress((void**)&wh,   g_wh);
    cudaGetSymbolAddress((void**)&lth,  g_lth);

    cudaFuncSetAttribute(gemm_async<DT, DL, 32, 3, 0>,
                         cudaFuncAttributeMaxDynamicSharedMemorySize, SMEM_P3);
    cudaFuncSetAttribute(gemm2_wide,
                         cudaFuncAttributeMaxDynamicSharedMemorySize, SMEM_G2);
    cudaFuncSetAttribute(gemm_async<LBL, DL, 64, 1, 2>,
                         cudaFuncAttributeMaxDynamicSharedMemorySize, SMEM_P1);

    // pre-split inputs to fp16 term pairs (labels split + transpose fused)
    split_k<<<(M_TOTAL * DT / 4 + 255) / 256, 256>>>(text, xh1, xh2, M_TOTAL * DT / 4);
    split_k<<<(DL * DT / 4 + 255) / 256, 256>>>(W, Wh1, Wh2, DL * DT / 4);
    labels_prep_k<<<dim3(DL / 32, LBL / 32), dim3(32, 8)>>>(labels);

    // K1: t = text @ W^T + b  (3-product) -> split-stored t
    gemm_async<DT, DL, 32, 3, 0><<<dim3(DL / 128, M_TOTAL / 128), 256, SMEM_P3>>>(
        xh1, xh2, Wh1, Wh2, b, nullptr);

    // K2: w = exp(threshold(sigmoid(t @ labels^T)))  (wide 128x256 tiles)
    gemm2_wide<<<dim3(LBL / 256, M_TOTAL / 128), 512, SMEM_G2>>>(th1, th2, lbh1, lbh2);

    // K3: out = (w @ labels) * inv  (champion shape; rowinv folded into prologue)
    gemm_async<LBL, DL, 64, 1, 2><<<dim3(DL / 128, M_TOTAL / 128), 256, SMEM_P1>>>(
        wh, nullptr, lth, nullptr, nullptr, out);
}

// round 17
// speedup vs baseline: 1.0485x; 1.0280x over previous
#include <cuda_runtime.h>
#include <cuda_fp16.h>
#include <cstdint>
#include <math.h>

#define M_TOTAL 16384
#define DT      1024
#define DL      768
#define LBL     4096
#define THRESH  0.4f

// ---------------- scratch (__device__ globals; no allocations allowed) ----------------
__device__ __half g_xh1[(size_t)M_TOTAL * DT];   // text split hi
__device__ __half g_xh2[(size_t)M_TOTAL * DT];   // text split lo
__device__ __half g_Wh1[(size_t)DL * DT];        // W split hi
__device__ __half g_Wh2[(size_t)DL * DT];        // W split lo
__device__ __half g_th1[(size_t)M_TOTAL * DL];   // t split hi
__device__ __half g_th2[(size_t)M_TOTAL * DL];   // t split lo
__device__ __half g_lbh1[(size_t)LBL * DL];      // labels split hi  [L][DL]
__device__ __half g_lbh2[(size_t)LBL * DL];      // labels split lo
__device__ __half g_wh[(size_t)M_TOTAL * LBL];   // softmax numerators fp16
__device__ __half g_lth[(size_t)DL * LBL];       // labels^T fp16 [DL][LBL]
__device__ float  g_part[(size_t)M_TOTAL * 64];  // per-row partial sums

// ---------------- PTX helpers ----------------
#define MMA16816(C, Ar, Br) \
    asm volatile("mma.sync.aligned.m16n8k16.row.col.f32.f16.f16.f32 " \
        "{%0,%1,%2,%3}, {%4,%5,%6,%7}, {%8,%9}, {%0,%1,%2,%3};" \
        : "+f"((C)[0]), "+f"((C)[1]), "+f"((C)[2]), "+f"((C)[3]) \
        : "r"((Ar)[0]), "r"((Ar)[1]), "r"((Ar)[2]), "r"((Ar)[3]), \
          "r"((Br)[0]), "r"((Br)[1]))

#define LDSM4(R0, R1, R2, R3, ADDR) \
    asm volatile("ldmatrix.sync.aligned.m8n8.x4.shared.b16 {%0,%1,%2,%3}, [%4];" \
        : "=r"(R0), "=r"(R1), "=r"(R2), "=r"(R3) : "r"(ADDR))

#define CPASYNC16(SMEM, GMEM) \
    asm volatile("cp.async.cg.shared.global [%0], [%1], 16;" \
        :: "r"(SMEM), "l"(GMEM))
#define CPCOMMIT() asm volatile("cp.async.commit_group;" ::: "memory")
#define CPWAIT(N)  asm volatile("cp.async.wait_group %0;" :: "n"(N) : "memory")

__device__ __forceinline__ uint32_t smem_u32(const void* p) {
    uint32_t a;
    asm("{ .reg .u64 t; cvta.to.shared.u64 t, %1; cvt.u32.u64 %0, t; }" : "=r"(a) : "l"(p));
    return a;
}

// ============ champion HMMA GEMM: 128x128 CTA, 256 thr, single-sync 2-stage ============
// NPROD=3: acc = A1*B1 + A2*B1 + A1*B2 (KT=32);  NPROD=1: acc = A1*B1 (KT=64).
// MODE 0: t = acc + bias -> split-store (g_th1,g_th2)            [GEMM1]
// MODE 2: out = acc * inv[m], inv from g_part in-prologue        [GEMM3]
template<int KDIM, int NDIM, int KT, int NPROD, int MODE>
__global__ __launch_bounds__(256, 2)
void gemm_async(const __half* __restrict__ A1p, const __half* __restrict__ A2p,
                const __half* __restrict__ B1p, const __half* __restrict__ B2p,
                const float* __restrict__ bias, float* __restrict__ outp)
{
    constexpr int NCH    = KDIM / KT;
    constexpr int STRIDE = KT + 8;            // halves per smem row (pad 16B)
    constexpr int TSIZE  = 128 * STRIDE;      // halves per tile
    constexpr int NT     = (NPROD == 3) ? 4 : 2;   // tiles: A1[,A2],B1[,B2]
    constexpr int TB1    = (NPROD == 3) ? 2 : 1;
    constexpr int CPT    = KT / 8;            // 16B segs per row
    constexpr int PERTHR = (128 * CPT) / 256; // cp.async per thread per tile

    extern __shared__ __align__(16) __half smh[];
    __shared__ float s_inv[128];
    const uint32_t smb = smem_u32(smh);

    const int tid  = threadIdx.x;
    const int wid  = tid >> 5;
    const int lane = tid & 31;
    const int g    = lane >> 2;
    const int tig  = lane & 3;
    const int wm   = wid & 3;
    const int wn   = wid >> 2;
    const int mrow = wm * 32;
    const int ncol = wn * 64;
    const int mBase = blockIdx.y * 128;
    const int nBase = blockIdx.x * 128;

    // MODE 2: fold old rowinv_k (same summation order -> bit-identical)
    if (MODE == 2 && tid < 128) {
        float s = 0.f;
        #pragma unroll
        for (int p = 0; p < 16; p++) s += g_part[(size_t)(mBase + tid) * 64 + p];
        s_inv[tid] = 1.f / s;
    }

    const __half* Tg[4];
    Tg[0] = A1p + (size_t)mBase * KDIM;
    if (NPROD == 3) {
        Tg[1] = A2p + (size_t)mBase * KDIM;
        Tg[2] = B1p + (size_t)nBase * KDIM;
        Tg[3] = B2p + (size_t)nBase * KDIM;
    } else {
        Tg[1] = B1p + (size_t)nBase * KDIM;
    }

    const int a_off = (mrow + (lane & 7) + ((lane >> 3) & 1) * 8) * STRIDE + ((lane >> 4) & 1) * 8;
    const int b_off = (ncol + (lane & 7) + ((lane >> 4) & 1) * 8) * STRIDE + ((lane >> 3) & 1) * 8;

    float acc[2][8][4];
    #pragma unroll
    for (int mt = 0; mt < 2; mt++)
        #pragma unroll
        for (int nt = 0; nt < 8; nt++)
            #pragma unroll
            for (int e = 0; e < 4; e++) acc[mt][nt][e] = 0.f;

    auto ISSUE = [&](int kb, int buf) {
        #pragma unroll
        for (int tl = 0; tl < NT; tl++) {
            #pragma unroll
            for (int t = 0; t < PERTHR; t++) {
                const int idx = tid + t * 256;
                const int r = idx / CPT, c16 = idx % CPT;
                const uint32_t sa = smb + ((buf * NT + tl) * TSIZE + r * STRIDE) * 2 + c16 * 16;
                const __half* ga = Tg[tl] + (size_t)r * KDIM + kb * KT + c16 * 8;
                CPASYNC16(sa, ga);
            }
        }
        CPCOMMIT();
    };

    ISSUE(0, 0);

    for (int kb = 0; kb < NCH; kb++) {
        const int buf = kb & 1;
        CPWAIT(0);                    // chunk kb resident
        __syncthreads();              // all warps past compute(kb-1) -> buf^1 free
        if (kb + 1 < NCH) ISSUE(kb + 1, buf ^ 1);

        const uint32_t tA1 = smb + ((buf * NT + 0) * TSIZE) * 2;
        const uint32_t tA2 = smb + ((buf * NT + 1) * TSIZE) * 2;
        const uint32_t tB1 = smb + ((buf * NT + TB1) * TSIZE) * 2;
        const uint32_t tB2 = smb + ((buf * NT + 3) * TSIZE) * 2;

        #pragma unroll
        for (int ks = 0; ks < KT; ks += 16) {
            uint32_t Af1[2][4], Af2[2][4], Bf[4][4];

            #pragma unroll
            for (int mt = 0; mt < 2; mt++)
                LDSM4(Af1[mt][0], Af1[mt][1], Af1[mt][2], Af1[mt][3],
                      tA1 + (a_off + mt * 16 * STRIDE + ks) * 2);
            if (NPROD == 3) {
                #pragma unroll
                for (int mt = 0; mt < 2; mt++)
                    LDSM4(Af2[mt][0], Af2[mt][1], Af2[mt][2], Af2[mt][3],
                          tA2 + (a_off + mt * 16 * STRIDE + ks) * 2);
            }
            #pragma unroll
            for (int p = 0; p < 4; p++)
                LDSM4(Bf[p][0], Bf[p][1], Bf[p][2], Bf[p][3],
                      tB1 + (b_off + p * 16 * STRIDE + ks) * 2);

            #pragma unroll
            for (int p = 0; p < 4; p++)
                #pragma unroll
                for (int mt = 0; mt < 2; mt++) {
                    MMA16816(acc[mt][p * 2 + 0], Af1[mt], &Bf[p][0]);
                    MMA16816(acc[mt][p * 2 + 1], Af1[mt], &Bf[p][2]);
                }

            if (NPROD == 3) {
                #pragma unroll
                for (int p = 0; p < 4; p++)
                    #pragma unroll
                    for (int mt = 0; mt < 2; mt++) {
                        MMA16816(acc[mt][p * 2 + 0], Af2[mt], &Bf[p][0]);
                        MMA16816(acc[mt][p * 2 + 1], Af2[mt], &Bf[p][2]);
                    }
                #pragma unroll
                for (int p = 0; p < 4; p++)
                    LDSM4(Bf[p][0], Bf[p][1], Bf[p][2], Bf[p][3],
                          tB2 + (b_off + p * 16 * STRIDE + ks) * 2);
                #pragma unroll
                for (int p = 0; p < 4; p++)
                    #pragma unroll
                    for (int mt = 0; mt < 2; mt++) {
                        MMA16816(acc[mt][p * 2 + 0], Af1[mt], &Bf[p][0]);
                        MMA16816(acc[mt][p * 2 + 1], Af1[mt], &Bf[p][2]);
                    }
            }
        }
    }

    // ---------------- epilogue ----------------
    #pragma unroll
    for (int mt = 0; mt < 2; mt++) {
        #pragma unroll
        for (int nt = 0; nt < 8; nt++) {
            const int lr0 = mrow + mt * 16 + g;
            const int lr1 = lr0 + 8;
            const int r0 = mBase + lr0, r1 = mBase + lr1;
            const int c  = nBase + ncol + nt * 8 + tig * 2;
            float v0 = acc[mt][nt][0], v1 = acc[mt][nt][1];
            float v2 = acc[mt][nt][2], v3 = acc[mt][nt][3];

            if (MODE == 0) {
                const float b0 = bias[c], b1 = bias[c + 1];
                v0 += b0; v1 += b1; v2 += b0; v3 += b1;
                __half2 h0 = __floats2half2_rn(v0, v1);
                __half2 h1 = __floats2half2_rn(v2, v3);
                float2 f0 = __half22float2(h0), f1 = __half22float2(h1);
                __half2 l0 = __floats2half2_rn(v0 - f0.x, v1 - f0.y);
                __half2 l1 = __floats2half2_rn(v2 - f1.x, v3 - f1.y);
                *(__half2*)(g_th1 + (size_t)r0 * NDIM + c) = h0;
                *(__half2*)(g_th1 + (size_t)r1 * NDIM + c) = h1;
                *(__half2*)(g_th2 + (size_t)r0 * NDIM + c) = l0;
                *(__half2*)(g_th2 + (size_t)r1 * NDIM + c) = l1;
            } else {
                const float i0 = s_inv[lr0], i1 = s_inv[lr1];
                *(float2*)(outp + (size_t)r0 * NDIM + c) = make_float2(v0 * i0, v1 * i0);
                *(float2*)(outp + (size_t)r1 * NDIM + c) = make_float2(v2 * i1, v3 * i1);
            }
        }
    }
}

// ============ GEMM2 wide: 128x256 CTA, 512 thr, KT=64, single-sync 2-stage ============
__global__ __launch_bounds__(512, 1)
void gemm2_wide(const __half* __restrict__ A1p, const __half* __restrict__ A2p,
                const __half* __restrict__ B1p, const __half* __restrict__ B2p)
{
    constexpr int KDIM = DL, NDIM = LBL, KT = 64;
    constexpr int NCH    = KDIM / KT;          // 12
    constexpr int STRIDE = KT + 8;             // 72
    constexpr int ASZ    = 128 * STRIDE;
    constexpr int BSZ    = 256 * STRIDE;
    constexpr int STG    = 2 * ASZ + 2 * BSZ;

    extern __shared__ __align__(16) __half smh[];
    const uint32_t smb = smem_u32(smh);

    const int tid  = threadIdx.x;
    const int wid  = tid >> 5;
    const int lane = tid & 31;
    const int g    = lane >> 2;
    const int tig  = lane & 3;
    const int wm   = wid & 3;
    const int wn   = wid >> 2;
    const int mrow = wm * 32;
    const int ncol = wn * 64;
    const int mBase = blockIdx.y * 128;
    const int nBase = blockIdx.x * 256;

    const __half* Ag1 = A1p + (size_t)mBase * KDIM;
    const __half* Ag2 = A2p + (size_t)mBase * KDIM;
    const __half* Bg1 = B1p + (size_t)nBase * KDIM;
    const __half* Bg2 = B2p + (size_t)nBase * KDIM;

    const int a_off = (mrow + (lane & 7) + ((lane >> 3) & 1) * 8) * STRIDE + ((lane >> 4) & 1) * 8;
    const int b_off = (ncol + (lane & 7) + ((lane >> 4) & 1) * 8) * STRIDE + ((lane >> 3) & 1) * 8;

    float acc[2][8][4];
    #pragma unroll
    for (int mt = 0; mt < 2; mt++)
        #pragma unroll
        for (int nt = 0; nt < 8; nt++)
            #pragma unroll
            for (int e = 0; e < 4; e++) acc[mt][nt][e] = 0.f;

    auto ISSUE = [&](int kb, int buf) {
        const uint32_t sbase = smb + (uint32_t)buf * STG * 2;
        #pragma unroll
        for (int t = 0; t < 2; t++) {
            const int idx = tid + t * 512;
            const int r = idx >> 3, c16 = idx & 7;
            CPASYNC16(sbase + (0 * ASZ + r * STRIDE) * 2 + c16 * 16,
                      Ag1 + (size_t)r * KDIM + kb * KT + c16 * 8);
        }
        #pragma unroll
        for (int t = 0; t < 2; t++) {
            const int idx = tid + t * 512;
            const int r = idx >> 3, c16 = idx & 7;
            CPASYNC16(sbase + (1 * ASZ + r * STRIDE) * 2 + c16 * 16,
                      Ag2 + (size_t)r * KDIM + kb * KT + c16 * 8);
        }
        #pragma unroll
        for (int t = 0; t < 4; t++) {
            const int idx = tid + t * 512;
            const int r = idx >> 3, c16 = idx & 7;
            CPASYNC16(sbase + (2 * ASZ + r * STRIDE) * 2 + c16 * 16,
                      Bg1 + (size_t)r * KDIM + kb * KT + c16 * 8);
        }
        #pragma unroll
        for (int t = 0; t < 4; t++) {
            const int idx = tid + t * 512;
            const int r = idx >> 3, c16 = idx & 7;
            CPASYNC16(sbase + (2 * ASZ + BSZ + r * STRIDE) * 2 + c16 * 16,
                      Bg2 + (size_t)r * KDIM + kb * KT + c16 * 8);
        }
        CPCOMMIT();
    };

    ISSUE(0, 0);

    for (int kb = 0; kb < NCH; kb++) {
        const int buf = kb & 1;
        CPWAIT(0);
        __syncthreads();
        if (kb + 1 < NCH) ISSUE(kb + 1, buf ^ 1);

        const uint32_t tA1 = smb + ((uint32_t)buf * STG + 0 * ASZ) * 2;
        const uint32_t tA2 = smb + ((uint32_t)buf * STG + 1 * ASZ) * 2;
        const uint32_t tB1 = smb + ((uint32_t)buf * STG + 2 * ASZ) * 2;
        const uint32_t tB2 = smb + ((uint32_t)buf * STG + 2 * ASZ + BSZ) * 2;

        #pragma unroll
        for (int ks = 0; ks < KT; ks += 16) {
            uint32_t Af1[2][4], Af2[2][4], Bf[4][4];

            #pragma unroll
            for (int mt = 0; mt < 2; mt++)
                LDSM4(Af1[mt][0], Af1[mt][1], Af1[mt][2], Af1[mt][3],
                      tA1 + (a_off + mt * 16 * STRIDE + ks) * 2);
            #pragma unroll
            for (int mt = 0; mt < 2; mt++)
                LDSM4(Af2[mt][0], Af2[mt][1], Af2[mt][2], Af2[mt][3],
                      tA2 + (a_off + mt * 16 * STRIDE + ks) * 2);
            #pragma unroll
            for (int p = 0; p < 4; p++)
                LDSM4(Bf[p][0], Bf[p][1], Bf[p][2], Bf[p][3],
                      tB1 + (b_off + p * 16 * STRIDE + ks) * 2);

            #pragma unroll
            for (int p = 0; p < 4; p++)
                #pragma unroll
                for (int mt = 0; mt < 2; mt++) {
                    MMA16816(acc[mt][p * 2 + 0], Af1[mt], &Bf[p][0]);
                    MMA16816(acc[mt][p * 2 + 1], Af1[mt], &Bf[p][2]);
                }
            #pragma unroll
            for (int p = 0; p < 4; p++)
                #pragma unroll
                for (int mt = 0; mt < 2; mt++) {
                    MMA16816(acc[mt][p * 2 + 0], Af2[mt], &Bf[p][0]);
                    MMA16816(acc[mt][p * 2 + 1], Af2[mt], &Bf[p][2]);
                }
            #pragma unroll
            for (int p = 0; p < 4; p++)
                LDSM4(Bf[p][0], Bf[p][1], Bf[p][2], Bf[p][3],
                      tB2 + (b_off + p * 16 * STRIDE + ks) * 2);
            #pragma unroll
            for (int p = 0; p < 4; p++)
                #pragma unroll
                for (int mt = 0; mt < 2; mt++) {
                    MMA16816(acc[mt][p * 2 + 0], Af1[mt], &Bf[p][0]);
                    MMA16816(acc[mt][p * 2 + 1], Af1[mt], &Bf[p][2]);
                }
        }
    }

    // ---- epilogue: sigmoid/threshold/exp + partial rowsums ----
    float rs[2][2] = {{0.f, 0.f}, {0.f, 0.f}};

    #pragma unroll
    for (int mt = 0; mt < 2; mt++) {
        #pragma unroll
        for (int nt = 0; nt < 8; nt++) {
            const int r0 = mBase + mrow + mt * 16 + g;
            const int r1 = r0 + 8;
            const int c  = nBase + ncol + nt * 8 + tig * 2;
            float v0 = acc[mt][nt][0], v1 = acc[mt][nt][1];
            float v2 = acc[mt][nt][2], v3 = acc[mt][nt][3];

            float a0 = __fdividef(1.f, 1.f + __expf(-v0)); if (a0 < THRESH) a0 = 0.f;
            float a1 = __fdividef(1.f, 1.f + __expf(-v1)); if (a1 < THRESH) a1 = 0.f;
            float a2 = __fdividef(1.f, 1.f + __expf(-v2)); if (a2 < THRESH) a2 = 0.f;
            float a3 = __fdividef(1.f, 1.f + __expf(-v3)); if (a3 < THRESH) a3 = 0.f;
            v0 = __expf(a0); v1 = __expf(a1); v2 = __expf(a2); v3 = __expf(a3);
            rs[mt][0] += v0 + v1;
            rs[mt][1] += v2 + v3;
            *(__half2*)(g_wh + (size_t)r0 * NDIM + c) = __floats2half2_rn(v0, v1);
            *(__half2*)(g_wh + (size_t)r1 * NDIM + c) = __floats2half2_rn(v2, v3);
        }
    }

    #pragma unroll
    for (int mt = 0; mt < 2; mt++)
        #pragma unroll
        for (int h = 0; h < 2; h++) {
            rs[mt][h] += __shfl_xor_sync(0xffffffffu, rs[mt][h], 1);
            rs[mt][h] += __shfl_xor_sync(0xffffffffu, rs[mt][h], 2);
        }
    __syncthreads();
    float* red = (float*)smh;                  // [128 rows][4 n-warps]
    if (tig == 0) {
        red[(mrow + g)      * 4 + wn] = rs[0][0];
        red[(mrow + g + 8)  * 4 + wn] = rs[0][1];
        red[(mrow + g + 16) * 4 + wn] = rs[1][0];
        red[(mrow + g + 24) * 4 + wn] = rs[1][1];
    }
    __syncthreads();
    if (tid < 128)
        g_part[(size_t)(mBase + tid) * 64 + blockIdx.x] =
            (red[tid * 4 + 0] + red[tid * 4 + 1]) + (red[tid * 4 + 2] + red[tid * 4 + 3]);
}

// ---------------- elementwise fp32 -> (h1,h2) split ----------------
__global__ void split_k(const float* __restrict__ src,
                        __half* __restrict__ d1, __half* __restrict__ d2, int n4)
{
    const int i = blockIdx.x * 256 + threadIdx.x;
    if (i >= n4) return;
    float4 x = ((const float4*)src)[i];
    __half2 h0 = __floats2half2_rn(x.x, x.y);
    __half2 h1 = __floats2half2_rn(x.z, x.w);
    float2 f0 = __half22float2(h0), f1 = __half22float2(h1);
    __half2 l0 = __floats2half2_rn(x.x - f0.x, x.y - f0.y);
    __half2 l1 = __floats2half2_rn(x.z - f1.x, x.w - f1.y);
    ((uint2*)d1)[i] = make_uint2(*(uint32_t*)&h0, *(uint32_t*)&h1);
    ((uint2*)d2)[i] = make_uint2(*(uint32_t*)&l0, *(uint32_t*)&l1);
}

// ------- fused labels pass: split -> (g_lbh1, g_lbh2)  AND  transpose -> g_lth -------
__global__ void labels_prep_k(const float* __restrict__ in)
{
    __shared__ float t[32][33];
    const int bx = blockIdx.x * 32;   // DL dim
    const int by = blockIdx.y * 32;   // LBL dim
    const int x = threadIdx.x, y = threadIdx.y;

    #pragma unroll
    for (int j = 0; j < 32; j += 8) {
        const size_t idx = (size_t)(by + y + j) * DL + bx + x;
        const float v = in[idx];
        t[y + j][x] = v;
        const __half h1 = __float2half_rn(v);
        const __half h2 = __float2half_rn(v - __half2float(h1));
        g_lbh1[idx] = h1;
        g_lbh2[idx] = h2;
    }
    __syncthreads();
    #pragma unroll
    for (int j = 0; j < 32; j += 8)
        g_lth[(size_t)(bx + y + j) * LBL + by + x] = __float2half_rn(t[x][y + j]);
}

// ============================ host launcher ============================
#define SMEM_P3 (2 * 4 * 128 * 40 * 2)     // 81920 B  (GEMM1: NPROD=3, KT=32)
#define SMEM_P1 (2 * 2 * 128 * 72 * 2)     // 73728 B  (GEMM3: NPROD=1, KT=64)
#define SMEM_G2 (2 * 55296 * 2)            // 221184 B (GEMM2 wide)

extern "C" void kernel_launch(void* const* d_in, const int* in_sizes, int n_in,
                              void* d_out, int out_size)
{
    const float* text   = (const float*)d_in[0];  // [8,2048,1024]
    const float* labels = (const float*)d_in[1];  // [4096,768]
    const float* W      = (const float*)d_in[2];  // [768,1024]
    const float* b      = (const float*)d_in[3];  // [768]
    float* out = (float*)d_out;                   // [8,2048,768]

    __half *xh1, *xh2, *Wh1, *Wh2, *th1, *th2, *lbh1, *lbh2, *wh, *lth;
    cudaGetSymbolAddress((void**)&xh1,  g_xh1);
    cudaGetSymbolAddress((void**)&xh2,  g_xh2);
    cudaGetSymbolAddress((void**)&Wh1,  g_Wh1);
    cudaGetSymbolAddress((void**)&Wh2,  g_Wh2);
    cudaGetSymbolAddress((void**)&th1,  g_th1);
    cudaGetSymbolAddress((void**)&th2,  g_th2);
    cudaGetSymbolAddress((void**)&lbh1, g_lbh1);
    cudaGetSymbolAddress((void**)&lbh2, g_lbh2);
    cudaGetSymbolAddress((void**)&wh,   g_wh);
    cudaGetSymbolAddress((void**)&lth,  g_lth);

    cudaFuncSetAttribute(gemm_async<DT, DL, 32, 3, 0>,
                         cudaFuncAttributeMaxDynamicSharedMemorySize, SMEM_P3);
    cudaFuncSetAttribute(gemm2_wide,
                         cudaFuncAttributeMaxDynamicSharedMemorySize, SMEM_G2);
    cudaFuncSetAttribute(gemm_async<LBL, DL, 64, 1, 2>,
                         cudaFuncAttributeMaxDynamicSharedMemorySize, SMEM_P1);

    // pre-split inputs to fp16 term pairs (labels split + transpose fused)
    split_k<<<(M_TOTAL * DT / 4 + 255) / 256, 256>>>(text, xh1, xh2, M_TOTAL * DT / 4);
    split_k<<<(DL * DT / 4 + 255) / 256, 256>>>(W, Wh1, Wh2, DL * DT / 4);
    labels_prep_k<<<dim3(DL / 32, LBL / 32), dim3(32, 8)>>>(labels);

    // K1: t = text @ W^T + b  (3-product) -> split-stored t
    gemm_async<DT, DL, 32, 3, 0><<<dim3(DL / 128, M_TOTAL / 128), 256, SMEM_P3>>>(
        xh1, xh2, Wh1, Wh2, b, nullptr);

    // K2: w = exp(threshold(sigmoid(t @ labels^T)))  (wide 128x256 tiles)
    gemm2_wide<<<dim3(LBL / 256, M_TOTAL / 128), 512, SMEM_G2>>>(th1, th2, lbh1, lbh2);

    // K3: out = (w @ labels) * inv  (champion shape; rowinv folded into prologue)
    gemm_async<LBL, DL, 64, 1, 2><<<dim3(DL / 128, M_TOTAL / 128), 256, SMEM_P1>>>(
        wh, nullptr, lth, nullptr, nullptr, out);
}